// round 2
// baseline (speedup 1.0000x reference)
#include <cuda_runtime.h>
#include <math.h>

#define BB 8
#define CC 512
#define HH 75
#define WW 100
#define PP 7500
#define KK 2000
#define FF 128

// ---------------- scratch (static device globals; no allocation) ----------------
__device__ int   g_sorted[BB * KK];
__device__ int   g_rank[BB * PP];
__device__ int   g_nbr[BB * KK * 9];
__device__ float g_nfT[(size_t)BB * CC * KK];   // [b][c][i]  (32.8 MB)
__device__ float g_t1[BB * KK * FF];            // nf @ w1
__device__ float g_x1[BB * KK * FF];            // A @ t1 + b1
__device__ float g_s2[BB * KK * FF];            // A @ x1

// ---------------- block-wide exclusive scan (blockDim == 1024) ----------------
__device__ __forceinline__ int block_excl_scan(int v, int* warp_sums, int tid) {
    int lane = tid & 31, wid = tid >> 5;
    int x = v;
#pragma unroll
    for (int o = 1; o < 32; o <<= 1) {
        int y = __shfl_up_sync(0xFFFFFFFFu, x, o);
        if (lane >= o) x += y;
    }
    if (lane == 31) warp_sums[wid] = x;
    __syncthreads();
    if (wid == 0) {
        int s = warp_sums[lane];
        int orig = s;
#pragma unroll
        for (int o = 1; o < 32; o <<= 1) {
            int y = __shfl_up_sync(0xFFFFFFFFu, s, o);
            if (lane >= o) s += y;
        }
        warp_sums[lane] = s - orig;   // exclusive warp base
    }
    __syncthreads();
    return (x - v) + warp_sums[wid];
}

// ---------------- K1: per-batch top-2000 radix select + stable compaction ----------------
__global__ void __launch_bounds__(1024) topk_kernel(const float* __restrict__ pred,
                                                    float* __restrict__ out_idx) {
    int b = blockIdx.x;
    const float* sc = pred + (size_t)b * 3 * PP;   // channel 0 of predict[b]
    __shared__ unsigned keys[PP];
    __shared__ unsigned hist[256];
    __shared__ unsigned sh_prefix, sh_r;
    __shared__ int warp_sums[32];
    int tid = threadIdx.x;

    for (int i = tid; i < PP; i += 1024) {
        unsigned u = __float_as_uint(sc[i]);
        u = (u & 0x80000000u) ? ~u : (u | 0x80000000u);   // monotonic float->uint
        keys[i] = u;
    }
    for (int i = tid; i < PP; i += 1024) g_rank[b * PP + i] = -1;
    __syncthreads();

    unsigned prefix = 0, r = KK;
#pragma unroll
    for (int pass = 0; pass < 4; ++pass) {
        int shift = 24 - 8 * pass;
        unsigned mask_hi = (pass == 0) ? 0u : (0xFFFFFFFFu << (shift + 8));
        for (int i = tid; i < 256; i += 1024) hist[i] = 0;
        __syncthreads();
        for (int i = tid; i < PP; i += 1024) {
            unsigned u = keys[i];
            if ((u & mask_hi) == prefix)
                atomicAdd(&hist[(u >> shift) & 255u], 1u);
        }
        __syncthreads();
        if (tid == 0) {
            unsigned cum = 0; int bsel = 0;
            for (int bv = 255; bv >= 0; --bv) {
                unsigned h = hist[bv];
                if (cum + h >= r) { bsel = bv; break; }
                cum += h;
            }
            sh_prefix = prefix | ((unsigned)bsel << shift);
            sh_r = r - cum;
        }
        __syncthreads();
        prefix = sh_prefix; r = sh_r;
        __syncthreads();
    }
    unsigned T = prefix;  // exact threshold key; r elements == T must be taken (lowest idx first)

    // stable index-ordered compaction: thread t owns [t*8, t*8+8)
    int start = tid * 8;
    int cnt_gt = 0, cnt_eq = 0;
#pragma unroll
    for (int k = 0; k < 8; ++k) {
        int i = start + k;
        if (i < PP) {
            unsigned u = keys[i];
            cnt_gt += (u > T);
            cnt_eq += (u == T);
        }
    }
    int base_eq = block_excl_scan(cnt_eq, warp_sums, tid);
    __syncthreads();
    int need = (int)r - base_eq;
    if (need < 0) need = 0;
    if (need > cnt_eq) need = cnt_eq;
    int my_sel = cnt_gt + need;
    int base_out = block_excl_scan(my_sel, warp_sums, tid);

    int pos = base_out, eqr = base_eq;
    for (int k = 0; k < 8; ++k) {
        int i = start + k;
        if (i >= PP) break;
        unsigned u = keys[i];
        bool sel = (u > T);
        if (u == T) { if (eqr < (int)r) sel = true; eqr++; }
        if (sel) {
            g_sorted[b * KK + pos] = i;
            if (out_idx) out_idx[b * KK + pos] = (float)i;
            g_rank[b * PP + i] = pos;
            pos++;
        }
    }
}

// ---------------- K2: 3x3 spatial neighbor lists (rank indices, -1 = absent) ----------------
__global__ void nbr_kernel() {
    int t = blockIdx.x * blockDim.x + threadIdx.x;
    if (t >= BB * KK) return;
    int b = t / KK;
    int s = g_sorted[t];
    int py = s / WW, px = s % WW;     // adjacency uses s//W, s%W
#pragma unroll
    for (int q = 0; q < 9; ++q) {
        int dy = q / 3 - 1, dx = q % 3 - 1;
        int ny = py + dy, nx = px + dx;
        int v = -1;
        if (ny >= 0 && ny < HH && nx >= 0 && nx < WW)
            v = g_rank[b * PP + ny * WW + nx];
        g_nbr[t * 9 + q] = v;
    }
}

// ---------------- K3: gather clipped features, transposed layout nfT[b][c][i] ----------------
__global__ void __launch_bounds__(256) gather_kernel(const float* __restrict__ feat) {
    int bc = blockIdx.x;          // b*512 + c
    int b = bc >> 9;
    __shared__ float plane[PP];
    const float* src = feat + (size_t)bc * PP;
    for (int i = threadIdx.x; i < PP; i += 256) plane[i] = src[i];
    __syncthreads();
    float* dst = g_nfT + (size_t)bc * KK;
    const int* si = g_sorted + b * KK;
    for (int i = threadIdx.x; i < KK; i += 256) {
        int s = si[i];
        int y = s % HH;           // feature gather uses s % H, s / H  (H=75)
        int x = s / HH;
        float v = plane[y * WW + x];
        v = fminf(fmaxf(v, 0.0f), 6.0f);
        dst[i] = v;
    }
}

// ---------------- K4: GEMM1  t1[i][f] = sum_c nfT[c][i] * w1[c][f] ----------------
__global__ void __launch_bounds__(256) gemm1_kernel(const float* __restrict__ w1) {
    int b = blockIdx.y;
    int i0 = blockIdx.x * 64;
    __shared__ float As[16][64];
    __shared__ float Bs[16][128];
    int tid = threadIdx.x;
    int tx = tid & 15;       // f group: f = tx + 16*j
    int ty = tid >> 4;       // i group: i = i0 + ty*4 + r

    float acc[4][8];
#pragma unroll
    for (int rI = 0; rI < 4; ++rI)
#pragma unroll
        for (int cI = 0; cI < 8; ++cI) acc[rI][cI] = 0.0f;

    const float* nfb = g_nfT + (size_t)b * CC * KK;
    for (int c0 = 0; c0 < CC; c0 += 16) {
#pragma unroll
        for (int j = 0; j < 4; ++j) {
            int kk = (tid >> 6) + j * 4;
            int ii = tid & 63;
            int gi = i0 + ii;
            As[kk][ii] = (gi < KK) ? nfb[(size_t)(c0 + kk) * KK + gi] : 0.0f;
        }
#pragma unroll
        for (int j = 0; j < 8; ++j) {
            int idx = tid + j * 256;
            int kk = idx >> 7, ff = idx & 127;
            Bs[kk][ff] = w1[(c0 + kk) * FF + ff];
        }
        __syncthreads();
#pragma unroll
        for (int kk = 0; kk < 16; ++kk) {
            float a[4], bv[8];
#pragma unroll
            for (int j = 0; j < 4; ++j) a[j] = As[kk][ty * 4 + j];
#pragma unroll
            for (int j = 0; j < 8; ++j) bv[j] = Bs[kk][tx + 16 * j];
#pragma unroll
            for (int rI = 0; rI < 4; ++rI)
#pragma unroll
                for (int cI = 0; cI < 8; ++cI) acc[rI][cI] += a[rI] * bv[cI];
        }
        __syncthreads();
    }
    float* t1b = g_t1 + b * KK * FF;
#pragma unroll
    for (int rI = 0; rI < 4; ++rI) {
        int gi = i0 + ty * 4 + rI;
        if (gi < KK) {
#pragma unroll
            for (int cI = 0; cI < 8; ++cI)
                t1b[gi * FF + tx + 16 * cI] = acc[rI][cI];
        }
    }
}

// ---------------- K5: x1 = A @ t1 + b1 (sparse neighbor sum) ----------------
__global__ void __launch_bounds__(128) x1_kernel(const float* __restrict__ b1) {
    int bi = blockIdx.x;                 // b*KK + i
    int b = bi / KK, i = bi % KK;
    int f = threadIdx.x;
    float s = b1[i * FF + f];
    const int* nb = g_nbr + bi * 9;
    const float* t1b = g_t1 + b * KK * FF;
#pragma unroll
    for (int q = 0; q < 9; ++q) {
        int j = nb[q];
        if (j >= 0) s += t1b[j * FF + f];
    }
    g_x1[bi * FF + f] = s;
}

// ---------------- K5b: s2 = A @ x1 ----------------
__global__ void __launch_bounds__(128) s2_kernel() {
    int bi = blockIdx.x;
    int b = bi / KK;
    int f = threadIdx.x;
    float s = 0.0f;
    const int* nb = g_nbr + bi * 9;
    const float* x1b = g_x1 + b * KK * FF;
#pragma unroll
    for (int q = 0; q < 9; ++q) {
        int j = nb[q];
        if (j >= 0) s += x1b[j * FF + f];
    }
    g_s2[bi * FF + f] = s;
}

// ---------------- K6: out = tanh(s2 @ w2 + b2 + x1) ----------------
__global__ void __launch_bounds__(256) gemm2_kernel(const float* __restrict__ w2,
                                                    const float* __restrict__ b2,
                                                    float* __restrict__ out) {
    int b = blockIdx.y;
    int i0 = blockIdx.x * 64;
    __shared__ float As[64][33];    // padded, A tile of s2 (row-major)
    __shared__ float Bs[32][128];
    int tid = threadIdx.x;
    int tx = tid & 15;
    int ty = tid >> 4;

    float acc[4][8];
#pragma unroll
    for (int rI = 0; rI < 4; ++rI)
#pragma unroll
        for (int cI = 0; cI < 8; ++cI) acc[rI][cI] = 0.0f;

    const float* s2b = g_s2 + b * KK * FF;
    for (int f0 = 0; f0 < FF; f0 += 32) {
#pragma unroll
        for (int j = 0; j < 8; ++j) {
            int idx = tid + j * 256;
            int row = idx >> 5, col = idx & 31;
            int gi = i0 + row;
            As[row][col] = (gi < KK) ? s2b[gi * FF + f0 + col] : 0.0f;
        }
#pragma unroll
        for (int j = 0; j < 16; ++j) {
            int idx = tid + j * 256;
            int kk = idx >> 7, gg = idx & 127;
            Bs[kk][gg] = w2[(f0 + kk) * FF + gg];
        }
        __syncthreads();
#pragma unroll
        for (int kk = 0; kk < 32; ++kk) {
            float a[4], bv[8];
#pragma unroll
            for (int j = 0; j < 4; ++j) a[j] = As[ty * 4 + j][kk];
#pragma unroll
            for (int j = 0; j < 8; ++j) bv[j] = Bs[kk][tx + 16 * j];
#pragma unroll
            for (int rI = 0; rI < 4; ++rI)
#pragma unroll
                for (int cI = 0; cI < 8; ++cI) acc[rI][cI] += a[rI] * bv[cI];
        }
        __syncthreads();
    }
    const float* x1b = g_x1 + b * KK * FF;
#pragma unroll
    for (int rI = 0; rI < 4; ++rI) {
        int gi = i0 + ty * 4 + rI;
        if (gi < KK) {
#pragma unroll
            for (int cI = 0; cI < 8; ++cI) {
                int ff = tx + 16 * cI;
                float v = acc[rI][cI] + b2[gi * FF + ff] + x1b[gi * FF + ff];
                out[((size_t)b * KK + gi) * FF + ff] = tanhf(v);
            }
        }
    }
}

// ---------------- launch ----------------
extern "C" void kernel_launch(void* const* d_in, const int* in_sizes, int n_in,
                              void* d_out, int out_size) {
    const float* feat = (const float*)d_in[0];   // (8,512,75,100)
    const float* pred = (const float*)d_in[1];   // (8,3,75,100)
    const float* w1   = (const float*)d_in[2];   // (512,128)
    const float* b1   = (const float*)d_in[3];   // (2000,128)
    const float* w2   = (const float*)d_in[4];   // (128,128)
    const float* b2   = (const float*)d_in[5];   // (2000,128)
    float* out = (float*)d_out;

    const int feat_elems = BB * KK * FF;         // 2,048,000
    float* out_idx = (out_size >= feat_elems + BB * KK) ? (out + feat_elems) : (float*)0;

    topk_kernel<<<BB, 1024>>>(pred, out_idx);
    nbr_kernel<<<(BB * KK + 255) / 256, 256>>>();
    gather_kernel<<<BB * CC, 256>>>(feat);
    {
        dim3 grid((KK + 63) / 64, BB);
        gemm1_kernel<<<grid, 256>>>(w1);
    }
    x1_kernel<<<BB * KK, 128>>>(b1);
    s2_kernel<<<BB * KK, 128>>>();
    {
        dim3 grid((KK + 63) / 64, BB);
        gemm2_kernel<<<grid, 256>>>(w2, b2, out);
    }
}

// round 5
// speedup vs baseline: 1.1023x; 1.1023x over previous
#include <cuda_runtime.h>
#include <math.h>

#define BB 8
#define CC 512
#define HH 75
#define WW 100
#define PP 7500
#define KK 2000
#define FF 128

typedef unsigned long long u64;

#define CLIP(x) fminf(fmaxf((x), 0.0f), 6.0f)

__device__ __forceinline__ u64 ffma2(u64 a, u64 b, u64 c) {
    u64 d;
    asm("fma.rn.f32x2 %0, %1, %2, %3;" : "=l"(d) : "l"(a), "l"(b), "l"(c));
    return d;
}
__device__ __forceinline__ u64 pack2(float x) {
    u64 r;
    asm("mov.b64 %0, {%1, %1};" : "=l"(r) : "f"(x));
    return r;
}

// ---------------- scratch ----------------
__device__ int   g_sorted[BB * KK];
__device__ int   g_rank[BB * PP];
__device__ int   g_nbr[BB * KK * 9];
__device__ int   g_pix[BB * KK];               // feature-gather pixel offset
__device__ float g_t1[BB * KK * FF];           // nf @ w1
__device__ float g_x1[BB * KK * FF];           // A @ t1 + b1
__device__ float g_s2[BB * KK * FF];           // A @ x1

// ---------------- block-wide exclusive scan (blockDim == 1024) ----------------
__device__ __forceinline__ int block_excl_scan(int v, int* warp_sums, int tid) {
    int lane = tid & 31, wid = tid >> 5;
    int x = v;
#pragma unroll
    for (int o = 1; o < 32; o <<= 1) {
        int y = __shfl_up_sync(0xFFFFFFFFu, x, o);
        if (lane >= o) x += y;
    }
    if (lane == 31) warp_sums[wid] = x;
    __syncthreads();
    if (wid == 0) {
        int s = warp_sums[lane];
        int orig = s;
#pragma unroll
        for (int o = 1; o < 32; o <<= 1) {
            int y = __shfl_up_sync(0xFFFFFFFFu, s, o);
            if (lane >= o) s += y;
        }
        warp_sums[lane] = s - orig;
    }
    __syncthreads();
    return (x - v) + warp_sums[wid];
}

// ---------------- K1: per-batch top-2000 radix select + stable compaction ----------------
__global__ void __launch_bounds__(1024) topk_kernel(const float* __restrict__ pred,
                                                    float* __restrict__ out_idx) {
    int b = blockIdx.x;
    const float* sc = pred + (size_t)b * 3 * PP;
    __shared__ unsigned keys[PP];
    __shared__ unsigned hist[256];
    __shared__ unsigned sh_prefix, sh_r;
    __shared__ int warp_sums[32];
    int tid = threadIdx.x;

    for (int i = tid; i < PP; i += 1024) {
        unsigned u = __float_as_uint(sc[i]);
        u = (u & 0x80000000u) ? ~u : (u | 0x80000000u);
        keys[i] = u;
    }
    for (int i = tid; i < PP; i += 1024) g_rank[b * PP + i] = -1;
    __syncthreads();

    unsigned prefix = 0, r = KK;
#pragma unroll
    for (int pass = 0; pass < 4; ++pass) {
        int shift = 24 - 8 * pass;
        unsigned mask_hi = (pass == 0) ? 0u : (0xFFFFFFFFu << (shift + 8));
        for (int i = tid; i < 256; i += 1024) hist[i] = 0;
        __syncthreads();
        for (int i = tid; i < PP; i += 1024) {
            unsigned u = keys[i];
            if ((u & mask_hi) == prefix)
                atomicAdd(&hist[(u >> shift) & 255u], 1u);
        }
        __syncthreads();
        if (tid == 0) {
            unsigned cum = 0; int bsel = 0;
            for (int bv = 255; bv >= 0; --bv) {
                unsigned h = hist[bv];
                if (cum + h >= r) { bsel = bv; break; }
                cum += h;
            }
            sh_prefix = prefix | ((unsigned)bsel << shift);
            sh_r = r - cum;
        }
        __syncthreads();
        prefix = sh_prefix; r = sh_r;
        __syncthreads();
    }
    unsigned T = prefix;

    int start = tid * 8;
    int cnt_gt = 0, cnt_eq = 0;
#pragma unroll
    for (int k = 0; k < 8; ++k) {
        int i = start + k;
        if (i < PP) {
            unsigned u = keys[i];
            cnt_gt += (u > T);
            cnt_eq += (u == T);
        }
    }
    int base_eq = block_excl_scan(cnt_eq, warp_sums, tid);
    __syncthreads();
    int need = (int)r - base_eq;
    if (need < 0) need = 0;
    if (need > cnt_eq) need = cnt_eq;
    int my_sel = cnt_gt + need;
    int base_out = block_excl_scan(my_sel, warp_sums, tid);

    int pos = base_out, eqr = base_eq;
    for (int k = 0; k < 8; ++k) {
        int i = start + k;
        if (i >= PP) break;
        unsigned u = keys[i];
        bool sel = (u > T);
        if (u == T) { if (eqr < (int)r) sel = true; eqr++; }
        if (sel) {
            g_sorted[b * KK + pos] = i;
            if (out_idx) out_idx[b * KK + pos] = (float)i;
            g_rank[b * PP + i] = pos;
            pos++;
        }
    }
}

// ---------------- K2: neighbor lists + feature pixel offsets ----------------
__global__ void nbr_kernel() {
    int t = blockIdx.x * blockDim.x + threadIdx.x;
    if (t >= BB * KK) return;
    int b = t / KK;
    int s = g_sorted[t];
    int py = s / WW, px = s % WW;            // adjacency coords
    g_pix[t] = (s % HH) * WW + (s / HH);     // feature-gather offset
#pragma unroll
    for (int q = 0; q < 9; ++q) {
        int dy = q / 3 - 1, dx = q % 3 - 1;
        int ny = py + dy, nx = px + dx;
        int v = -1;
        if (ny >= 0 && ny < HH && nx >= 0 && nx < WW)
            v = g_rank[b * PP + ny * WW + nx];
        g_nbr[t * 9 + q] = v;
    }
}

// ---------------- K3: fused gather + GEMM1  t1[i][f] = sum_c clip(feat)[c][i] * w1[c][f] ----------------
// tile: 128 i x 128 f, k-step 16; per-thread 8x8 via FFMA2; double-buffered.
__global__ void __launch_bounds__(256) gemm1_fused(const float* __restrict__ feat,
                                                   const float* __restrict__ w1) {
    __shared__ __align__(16) float As[2][16][128];
    __shared__ __align__(16) float Bs[2][16][128];
    __shared__ int pixS[128];
    int b = blockIdx.y, i0 = blockIdx.x * 128;
    int tid = threadIdx.x;
    int tx = tid & 15, ty = tid >> 4;
    int lk = tid >> 4, li = (tid & 15) * 8;

    if (tid < 128) {
        int gi = i0 + tid;
        pixS[tid] = (gi < KK) ? g_pix[b * KK + tid + i0] : 0;
    }
    __syncthreads();

    const float* fb = feat + (size_t)b * CC * PP;
    u64 acc[8][4];
#pragma unroll
    for (int r = 0; r < 8; ++r)
#pragma unroll
        for (int c = 0; c < 4; ++c) acc[r][c] = 0ull;

    float ra[8];
    float4 rb0, rb1;

    // prologue: load + store k-step 0
    {
        const float* fr = fb + (size_t)lk * PP;
#pragma unroll
        for (int j = 0; j < 8; ++j) ra[j] = fr[pixS[li + j]];
        const float* wr = w1 + lk * FF + li;
        rb0 = *(const float4*)wr;
        rb1 = *(const float4*)(wr + 4);
        *(float4*)&As[0][lk][li]     = make_float4(CLIP(ra[0]), CLIP(ra[1]), CLIP(ra[2]), CLIP(ra[3]));
        *(float4*)&As[0][lk][li + 4] = make_float4(CLIP(ra[4]), CLIP(ra[5]), CLIP(ra[6]), CLIP(ra[7]));
        *(float4*)&Bs[0][lk][li]     = rb0;
        *(float4*)&Bs[0][lk][li + 4] = rb1;
    }
    __syncthreads();

#pragma unroll 1
    for (int s = 0; s < 32; ++s) {
        int cur = s & 1;
        if (s < 31) {
            int c = (s + 1) * 16 + lk;
            const float* fr = fb + (size_t)c * PP;
#pragma unroll
            for (int j = 0; j < 8; ++j) ra[j] = fr[pixS[li + j]];
            const float* wr = w1 + c * FF + li;
            rb0 = *(const float4*)wr;
            rb1 = *(const float4*)(wr + 4);
        }
#pragma unroll
        for (int kk = 0; kk < 16; ++kk) {
            float4 a0 = *(const float4*)&As[cur][kk][ty * 8];
            float4 a1 = *(const float4*)&As[cur][kk][ty * 8 + 4];
            ulonglong2 q0 = *(const ulonglong2*)&Bs[cur][kk][tx * 8];
            ulonglong2 q1 = *(const ulonglong2*)&Bs[cur][kk][tx * 8 + 4];
            u64 bp0 = q0.x, bp1 = q0.y, bp2 = q1.x, bp3 = q1.y;
            float af[8] = {a0.x, a0.y, a0.z, a0.w, a1.x, a1.y, a1.z, a1.w};
#pragma unroll
            for (int r = 0; r < 8; ++r) {
                u64 ap = pack2(af[r]);
                acc[r][0] = ffma2(ap, bp0, acc[r][0]);
                acc[r][1] = ffma2(ap, bp1, acc[r][1]);
                acc[r][2] = ffma2(ap, bp2, acc[r][2]);
                acc[r][3] = ffma2(ap, bp3, acc[r][3]);
            }
        }
        if (s < 31) {
            int nb = (s + 1) & 1;
            *(float4*)&As[nb][lk][li]     = make_float4(CLIP(ra[0]), CLIP(ra[1]), CLIP(ra[2]), CLIP(ra[3]));
            *(float4*)&As[nb][lk][li + 4] = make_float4(CLIP(ra[4]), CLIP(ra[5]), CLIP(ra[6]), CLIP(ra[7]));
            *(float4*)&Bs[nb][lk][li]     = rb0;
            *(float4*)&Bs[nb][lk][li + 4] = rb1;
        }
        __syncthreads();
    }

    float* t1b = g_t1 + b * KK * FF;
#pragma unroll
    for (int r = 0; r < 8; ++r) {
        int gi = i0 + ty * 8 + r;
        if (gi < KK) {
            float* dst = t1b + gi * FF + tx * 8;
            *(float2*)(dst)     = *(float2*)&acc[r][0];
            *(float2*)(dst + 2) = *(float2*)&acc[r][1];
            *(float2*)(dst + 4) = *(float2*)&acc[r][2];
            *(float2*)(dst + 6) = *(float2*)&acc[r][3];
        }
    }
}

// ---------------- K4: x1 = A @ t1 + b1 ----------------
__global__ void __launch_bounds__(128) x1_kernel(const float* __restrict__ b1) {
    int bi = blockIdx.x;
    int b = bi / KK, i = bi % KK;
    int f = threadIdx.x;
    float s = b1[i * FF + f];
    const int* nb = g_nbr + bi * 9;
    const float* t1b = g_t1 + b * KK * FF;
#pragma unroll
    for (int q = 0; q < 9; ++q) {
        int j = nb[q];
        if (j >= 0) s += t1b[j * FF + f];
    }
    g_x1[bi * FF + f] = s;
}

// ---------------- K5: s2 = A @ x1 ----------------
__global__ void __launch_bounds__(128) s2_kernel() {
    int bi = blockIdx.x;
    int b = bi / KK;
    int f = threadIdx.x;
    float s = 0.0f;
    const int* nb = g_nbr + bi * 9;
    const float* x1b = g_x1 + b * KK * FF;
#pragma unroll
    for (int q = 0; q < 9; ++q) {
        int j = nb[q];
        if (j >= 0) s += x1b[j * FF + f];
    }
    g_s2[bi * FF + f] = s;
}

// ---------------- K6: out = tanh(s2 @ w2 + b2 + x1) ----------------
// tile 128 i x 128 f, k-step 16 (8 steps), FFMA2, fused epilogue.
__global__ void __launch_bounds__(256) gemm2_kernel(const float* __restrict__ w2,
                                                    const float* __restrict__ b2,
                                                    float* __restrict__ out) {
    __shared__ __align__(16) float As[2][128][20];   // [ii][kk], pad to 20 for 16B-aligned rows
    __shared__ __align__(16) float Bs[2][16][128];
    int b = blockIdx.y, i0 = blockIdx.x * 128;
    int tid = threadIdx.x;
    int tx = tid & 15, ty = tid >> 4;
    int ri = tid >> 1, cb = (tid & 1) * 8;
    int lk = tid >> 4, li = (tid & 15) * 8;

    const float* s2b = g_s2 + b * KK * FF;
    u64 acc[8][4];
#pragma unroll
    for (int r = 0; r < 8; ++r)
#pragma unroll
        for (int c = 0; c < 4; ++c) acc[r][c] = 0ull;

    float4 ua0, ua1, ub0, ub1;
    const float4 z4 = make_float4(0.f, 0.f, 0.f, 0.f);

    // prologue step 0 (f0 = 0)
    {
        int gi = i0 + ri;
        if (gi < KK) {
            const float* p = s2b + gi * FF + cb;
            ua0 = *(const float4*)p;
            ua1 = *(const float4*)(p + 4);
        } else { ua0 = z4; ua1 = z4; }
        const float* wr = w2 + lk * FF + li;
        ub0 = *(const float4*)wr;
        ub1 = *(const float4*)(wr + 4);
        *(float4*)&As[0][ri][cb]     = ua0;
        *(float4*)&As[0][ri][cb + 4] = ua1;
        *(float4*)&Bs[0][lk][li]     = ub0;
        *(float4*)&Bs[0][lk][li + 4] = ub1;
    }
    __syncthreads();

#pragma unroll 1
    for (int s = 0; s < 8; ++s) {
        int cur = s & 1;
        if (s < 7) {
            int f0 = (s + 1) * 16;
            int gi = i0 + ri;
            if (gi < KK) {
                const float* p = s2b + gi * FF + f0 + cb;
                ua0 = *(const float4*)p;
                ua1 = *(const float4*)(p + 4);
            } else { ua0 = z4; ua1 = z4; }
            const float* wr = w2 + (f0 + lk) * FF + li;
            ub0 = *(const float4*)wr;
            ub1 = *(const float4*)(wr + 4);
        }
#pragma unroll
        for (int kk = 0; kk < 16; ++kk) {
            ulonglong2 q0 = *(const ulonglong2*)&Bs[cur][kk][tx * 8];
            ulonglong2 q1 = *(const ulonglong2*)&Bs[cur][kk][tx * 8 + 4];
            u64 bp0 = q0.x, bp1 = q0.y, bp2 = q1.x, bp3 = q1.y;
#pragma unroll
            for (int r = 0; r < 8; ++r) {
                u64 ap = pack2(As[cur][ty * 8 + r][kk]);
                acc[r][0] = ffma2(ap, bp0, acc[r][0]);
                acc[r][1] = ffma2(ap, bp1, acc[r][1]);
                acc[r][2] = ffma2(ap, bp2, acc[r][2]);
                acc[r][3] = ffma2(ap, bp3, acc[r][3]);
            }
        }
        if (s < 7) {
            int nb = (s + 1) & 1;
            *(float4*)&As[nb][ri][cb]     = ua0;
            *(float4*)&As[nb][ri][cb + 4] = ua1;
            *(float4*)&Bs[nb][lk][li]     = ub0;
            *(float4*)&Bs[nb][lk][li + 4] = ub1;
        }
        __syncthreads();
    }

    const float* x1b = g_x1 + b * KK * FF;
#pragma unroll
    for (int r = 0; r < 8; ++r) {
        int gi = i0 + ty * 8 + r;
        if (gi < KK) {
            int base = gi * FF + tx * 8;
            float* dst = out + (size_t)b * KK * FF + base;
#pragma unroll
            for (int c = 0; c < 4; ++c) {
                float2 v  = *(float2*)&acc[r][c];
                float2 bb = *(const float2*)&b2[base + 2 * c];
                float2 xx = *(const float2*)&x1b[base + 2 * c];
                float2 o;
                o.x = tanhf(v.x + bb.x + xx.x);
                o.y = tanhf(v.y + bb.y + xx.y);
                *(float2*)(dst + 2 * c) = o;
            }
        }
    }
}

// ---------------- launch ----------------
extern "C" void kernel_launch(void* const* d_in, const int* in_sizes, int n_in,
                              void* d_out, int out_size) {
    const float* feat = (const float*)d_in[0];
    const float* pred = (const float*)d_in[1];
    const float* w1   = (const float*)d_in[2];
    const float* b1   = (const float*)d_in[3];
    const float* w2   = (const float*)d_in[4];
    const float* b2   = (const float*)d_in[5];
    float* out = (float*)d_out;

    const int feat_elems = BB * KK * FF;
    float* out_idx = (out_size >= feat_elems + BB * KK) ? (out + feat_elems) : (float*)0;

    topk_kernel<<<BB, 1024>>>(pred, out_idx);
    nbr_kernel<<<(BB * KK + 255) / 256, 256>>>();
    {
        dim3 grid((KK + 127) / 128, BB);
        gemm1_fused<<<grid, 256>>>(feat, w1);
    }
    x1_kernel<<<BB * KK, 128>>>(b1);
    s2_kernel<<<BB * KK, 128>>>();
    {
        dim3 grid((KK + 127) / 128, BB);
        gemm2_kernel<<<grid, 256>>>(w2, b2, out);
    }
}

// round 7
// speedup vs baseline: 1.4786x; 1.3414x over previous
#include <cuda_runtime.h>
#include <math.h>

#define BB 8
#define CC 512
#define HH 75
#define WW 100
#define PP 7500
#define KK 2000
#define FF 128

typedef unsigned long long u64;
typedef unsigned int u32;

#define CLIP(x) fminf(fmaxf((x), 0.0f), 6.0f)

__device__ __forceinline__ u64 ffma2(u64 a, u64 b, u64 c) {
    u64 d;
    asm("fma.rn.f32x2 %0, %1, %2, %3;" : "=l"(d) : "l"(a), "l"(b), "l"(c));
    return d;
}
__device__ __forceinline__ u64 pack2(float x) {
    u64 r;
    asm("mov.b64 %0, {%1, %1};" : "=l"(r) : "f"(x));
    return r;
}
__device__ __forceinline__ u32 f2tf32(float x) {
    u32 u;
    asm("cvt.rna.tf32.f32 %0, %1;" : "=r"(u) : "f"(x));
    return u;
}
__device__ __forceinline__ void mma8(float* d, u32 a0, u32 a1, u32 a2, u32 a3,
                                     u32 b0, u32 b1) {
    asm volatile(
        "mma.sync.aligned.m16n8k8.row.col.f32.tf32.tf32.f32 "
        "{%0,%1,%2,%3}, {%4,%5,%6,%7}, {%8,%9}, {%0,%1,%2,%3};"
        : "+f"(d[0]), "+f"(d[1]), "+f"(d[2]), "+f"(d[3])
        : "r"(a0), "r"(a1), "r"(a2), "r"(a3), "r"(b0), "r"(b1));
}

// ---------------- scratch ----------------
__device__ int   g_sorted[BB * KK];
__device__ int   g_rank[BB * PP];
__device__ int   g_nbr[BB * KK * 9];
__device__ int   g_pix[BB * KK];
__device__ float g_t1[BB * KK * FF];
__device__ float g_x1[BB * KK * FF];
__device__ float g_s2[BB * KK * FF];
// w1 in mma-fragment order: [kb(64)][ntg(16)][lane(32)] = {b0_hi, b1_hi, b0_lo, b1_lo}
__device__ uint4 g_w1f4[64 * 16 * 32];

// ---------------- block-wide exclusive scan (blockDim == 1024) ----------------
__device__ __forceinline__ int block_excl_scan(int v, int* warp_sums, int tid) {
    int lane = tid & 31, wid = tid >> 5;
    int x = v;
#pragma unroll
    for (int o = 1; o < 32; o <<= 1) {
        int y = __shfl_up_sync(0xFFFFFFFFu, x, o);
        if (lane >= o) x += y;
    }
    if (lane == 31) warp_sums[wid] = x;
    __syncthreads();
    if (wid == 0) {
        int s = warp_sums[lane];
        int orig = s;
#pragma unroll
        for (int o = 1; o < 32; o <<= 1) {
            int y = __shfl_up_sync(0xFFFFFFFFu, s, o);
            if (lane >= o) s += y;
        }
        warp_sums[lane] = s - orig;
    }
    __syncthreads();
    return (x - v) + warp_sums[wid];
}

// ---------------- K0: split w1 into tf32 hi/lo fragment table ----------------
__global__ void __launch_bounds__(256) prep_w1(const float* __restrict__ w1) {
    int t = blockIdx.x * blockDim.x + threadIdx.x;
    if (t >= 64 * 16 * 32) return;
    int lane = t & 31;
    int ntg  = (t >> 5) & 15;
    int kb   = t >> 9;
    int n  = ntg * 8 + (lane >> 2);
    int k0 = kb * 8 + (lane & 3);
    float v0 = w1[k0 * FF + n];
    float v1 = w1[(k0 + 4) * FF + n];
    u32 h0 = f2tf32(v0);
    u32 h1 = f2tf32(v1);
    u32 l0 = f2tf32(v0 - __uint_as_float(h0));
    u32 l1 = f2tf32(v1 - __uint_as_float(h1));
    g_w1f4[t] = make_uint4(h0, h1, l0, l1);
}

// ---------------- K1: per-batch top-2000 radix select + stable compaction ----------------
__global__ void __launch_bounds__(1024) topk_kernel(const float* __restrict__ pred,
                                                    float* __restrict__ out_idx) {
    int b = blockIdx.x;
    const float* sc = pred + (size_t)b * 3 * PP;
    __shared__ unsigned keys[PP];
    __shared__ unsigned hist[256];
    __shared__ int sh_bin;
    __shared__ unsigned sh_r2;
    __shared__ int warp_sums[32];
    int tid = threadIdx.x;

    for (int i = tid; i < PP; i += 1024) {
        unsigned u = __float_as_uint(sc[i]);
        u = (u & 0x80000000u) ? ~u : (u | 0x80000000u);
        keys[i] = u;
    }
    for (int i = tid; i < PP; i += 1024) g_rank[b * PP + i] = -1;
    __syncthreads();

    unsigned prefix = 0, r = KK;
#pragma unroll
    for (int pass = 0; pass < 4; ++pass) {
        int shift = 24 - 8 * pass;
        unsigned mask_hi = (pass == 0) ? 0u : (0xFFFFFFFFu << (shift + 8));
        for (int i = tid; i < 256; i += 1024) hist[i] = 0;
        __syncthreads();
        for (int i = tid; i < PP; i += 1024) {
            unsigned u = keys[i];
            if ((u & mask_hi) == prefix)
                atomicAdd(&hist[(u >> shift) & 255u], 1u);
        }
        __syncthreads();
        // parallel descending-bin selection
        int v = (tid < 256) ? (int)hist[255 - tid] : 0;
        int ex = block_excl_scan(v, warp_sums, tid);
        if (tid < 256 && ex < (int)r && ex + v >= (int)r) {
            sh_bin = 255 - tid;
            sh_r2  = r - (unsigned)ex;
        }
        __syncthreads();
        prefix |= ((unsigned)sh_bin) << shift;
        r = sh_r2;
        __syncthreads();
    }
    unsigned T = prefix;

    int start = tid * 8;
    int cnt_gt = 0, cnt_eq = 0;
#pragma unroll
    for (int k = 0; k < 8; ++k) {
        int i = start + k;
        if (i < PP) {
            unsigned u = keys[i];
            cnt_gt += (u > T);
            cnt_eq += (u == T);
        }
    }
    int base_eq = block_excl_scan(cnt_eq, warp_sums, tid);
    __syncthreads();
    int need = (int)r - base_eq;
    if (need < 0) need = 0;
    if (need > cnt_eq) need = cnt_eq;
    int my_sel = cnt_gt + need;
    int base_out = block_excl_scan(my_sel, warp_sums, tid);

    int pos = base_out, eqr = base_eq;
    for (int k = 0; k < 8; ++k) {
        int i = start + k;
        if (i >= PP) break;
        unsigned u = keys[i];
        bool sel = (u > T);
        if (u == T) { if (eqr < (int)r) sel = true; eqr++; }
        if (sel) {
            g_sorted[b * KK + pos] = i;
            if (out_idx) out_idx[b * KK + pos] = (float)i;
            g_rank[b * PP + i] = pos;
            pos++;
        }
    }
}

// ---------------- K2: neighbor lists + feature pixel offsets ----------------
__global__ void nbr_kernel() {
    int t = blockIdx.x * blockDim.x + threadIdx.x;
    if (t >= BB * KK) return;
    int b = t / KK;
    int s = g_sorted[t];
    int py = s / WW, px = s % WW;
    g_pix[t] = (s % HH) * WW + (s / HH);
#pragma unroll
    for (int q = 0; q < 9; ++q) {
        int dy = q / 3 - 1, dx = q % 3 - 1;
        int ny = py + dy, nx = px + dx;
        int v = -1;
        if (ny >= 0 && ny < HH && nx >= 0 && nx < WW)
            v = g_rank[b * PP + ny * WW + nx];
        g_nbr[t * 9 + q] = v;
    }
}

// ---------------- K3: fused gather + GEMM1 on tensor cores (split tf32) ----------------
// t1[i][f] = sum_c clip(feat)[c][i] * w1[c][f]
// CTA tile 128i x 128f, K=512 in 32 stages of 16 channels; 8 warps = 2(m) x 4(n),
// warp tile 64x32. A staged hi/lo in smem [k][m] (pad 136, conflict-free);
// B frags direct LDG.128 from g_w1f4. 3 MMAs per tile: hh + hl + lh.
#define APAD 136
__global__ void __launch_bounds__(256, 1) gemm1_mma(const float* __restrict__ feat) {
    __shared__ u32 Ah[2][16 * APAD];
    __shared__ u32 Al[2][16 * APAD];
    __shared__ int pixS[128];
    int b = blockIdx.y, i0 = blockIdx.x * 128;
    int tid = threadIdx.x;
    int lane = tid & 31, warp = tid >> 5;
    int wm = warp & 1, wn = warp >> 1;       // 2 x 4 warp grid
    int lk = tid >> 4, li = (tid & 15) * 8;  // loader: row lk (channel), 8 pixels

    if (tid < 128) {
        int gi = i0 + tid;
        pixS[tid] = (gi < KK) ? g_pix[b * KK + gi] : 0;
    }
    __syncthreads();

    const float* fb = feat + (size_t)b * CC * PP;
    float acc[4][4][4];
#pragma unroll
    for (int mt = 0; mt < 4; ++mt)
#pragma unroll
        for (int nt = 0; nt < 4; ++nt)
#pragma unroll
            for (int e = 0; e < 4; ++e) acc[mt][nt][e] = 0.0f;

    // prologue: stage 0
    {
        const float* fr = fb + (size_t)lk * PP;
        float ra[8];
#pragma unroll
        for (int j = 0; j < 8; ++j) ra[j] = CLIP(fr[pixS[li + j]]);
        u32 h[8], l[8];
#pragma unroll
        for (int j = 0; j < 8; ++j) {
            h[j] = f2tf32(ra[j]);
            l[j] = f2tf32(ra[j] - __uint_as_float(h[j]));
        }
        *(uint4*)&Ah[0][lk * APAD + li]     = make_uint4(h[0], h[1], h[2], h[3]);
        *(uint4*)&Ah[0][lk * APAD + li + 4] = make_uint4(h[4], h[5], h[6], h[7]);
        *(uint4*)&Al[0][lk * APAD + li]     = make_uint4(l[0], l[1], l[2], l[3]);
        *(uint4*)&Al[0][lk * APAD + li + 4] = make_uint4(l[4], l[5], l[6], l[7]);
    }
    __syncthreads();

    int r4 = lane >> 2, c4 = lane & 3;

#pragma unroll 1
    for (int s = 0; s < 32; ++s) {
        int cur = s & 1;
        float ra[8];
        if (s < 31) {
            const float* fr = fb + (size_t)((s + 1) * 16 + lk) * PP;
#pragma unroll
            for (int j = 0; j < 8; ++j) ra[j] = CLIP(fr[pixS[li + j]]);
        }
        // B fragments for this stage (L2-resident table)
        uint4 bf[2][4];
#pragma unroll
        for (int kq = 0; kq < 2; ++kq)
#pragma unroll
            for (int nt = 0; nt < 4; ++nt)
                bf[kq][nt] = g_w1f4[(((2 * s + kq) * 16) + wn * 4 + nt) * 32 + lane];

#pragma unroll
        for (int kq = 0; kq < 2; ++kq) {
#pragma unroll
            for (int mt = 0; mt < 4; ++mt) {
                int mb = wm * 64 + mt * 16 + r4;
                int k0 = (kq * 8 + c4) * APAD;
                int k4 = (kq * 8 + 4 + c4) * APAD;
                u32 ah0 = Ah[cur][k0 + mb];
                u32 ah1 = Ah[cur][k0 + mb + 8];
                u32 ah2 = Ah[cur][k4 + mb];
                u32 ah3 = Ah[cur][k4 + mb + 8];
                u32 al0 = Al[cur][k0 + mb];
                u32 al1 = Al[cur][k0 + mb + 8];
                u32 al2 = Al[cur][k4 + mb];
                u32 al3 = Al[cur][k4 + mb + 8];
#pragma unroll
                for (int nt = 0; nt < 4; ++nt) {
                    uint4 bb = bf[kq][nt];
                    mma8(acc[mt][nt], ah0, ah1, ah2, ah3, bb.x, bb.y);  // hi*hi
                    mma8(acc[mt][nt], ah0, ah1, ah2, ah3, bb.z, bb.w);  // hi*lo
                    mma8(acc[mt][nt], al0, al1, al2, al3, bb.x, bb.y);  // lo*hi
                }
            }
        }
        if (s < 31) {
            int nb = (s + 1) & 1;
            u32 h[8], l[8];
#pragma unroll
            for (int j = 0; j < 8; ++j) {
                h[j] = f2tf32(ra[j]);
                l[j] = f2tf32(ra[j] - __uint_as_float(h[j]));
            }
            *(uint4*)&Ah[nb][lk * APAD + li]     = make_uint4(h[0], h[1], h[2], h[3]);
            *(uint4*)&Ah[nb][lk * APAD + li + 4] = make_uint4(h[4], h[5], h[6], h[7]);
            *(uint4*)&Al[nb][lk * APAD + li]     = make_uint4(l[0], l[1], l[2], l[3]);
            *(uint4*)&Al[nb][lk * APAD + li + 4] = make_uint4(l[4], l[5], l[6], l[7]);
        }
        __syncthreads();
    }

    float* t1b = g_t1 + b * KK * FF;
#pragma unroll
    for (int mt = 0; mt < 4; ++mt) {
#pragma unroll
        for (int nt = 0; nt < 4; ++nt) {
            int m = wm * 64 + mt * 16 + r4;
            int n = wn * 32 + nt * 8 + 2 * c4;
            int gi = i0 + m;
            if (gi < KK)
                *(float2*)&t1b[gi * FF + n] = make_float2(acc[mt][nt][0], acc[mt][nt][1]);
            int gi8 = gi + 8;
            if (gi8 < KK)
                *(float2*)&t1b[gi8 * FF + n] = make_float2(acc[mt][nt][2], acc[mt][nt][3]);
        }
    }
}

// ---------------- K4: x1 = A @ t1 + b1 (float4, 8 rows/block) ----------------
__global__ void __launch_bounds__(256) x1_kernel(const float* __restrict__ b1) {
    int r = blockIdx.x * 8 + (threadIdx.x >> 5);
    int lane = threadIdx.x & 31;
    int b = r / KK, i = r % KK;
    const int* nb = g_nbr + r * 9;
    const float* t1b = g_t1 + b * KK * FF;
    float4 s = *(const float4*)&b1[i * FF + lane * 4];
#pragma unroll
    for (int q = 0; q < 9; ++q) {
        int j = nb[q];
        if (j >= 0) {
            float4 t = *(const float4*)&t1b[j * FF + lane * 4];
            s.x += t.x; s.y += t.y; s.z += t.z; s.w += t.w;
        }
    }
    *(float4*)&g_x1[r * FF + lane * 4] = s;
}

// ---------------- K5: s2 = A @ x1 ----------------
__global__ void __launch_bounds__(256) s2_kernel() {
    int r = blockIdx.x * 8 + (threadIdx.x >> 5);
    int lane = threadIdx.x & 31;
    int b = r / KK;
    const int* nb = g_nbr + r * 9;
    const float* x1b = g_x1 + b * KK * FF;
    float4 s = make_float4(0.f, 0.f, 0.f, 0.f);
#pragma unroll
    for (int q = 0; q < 9; ++q) {
        int j = nb[q];
        if (j >= 0) {
            float4 t = *(const float4*)&x1b[j * FF + lane * 4];
            s.x += t.x; s.y += t.y; s.z += t.z; s.w += t.w;
        }
    }
    *(float4*)&g_s2[r * FF + lane * 4] = s;
}

// ---------------- K6: out = tanh(s2 @ w2 + b2 + x1) (FFMA2) ----------------
__global__ void __launch_bounds__(256) gemm2_kernel(const float* __restrict__ w2,
                                                    const float* __restrict__ b2,
                                                    float* __restrict__ out) {
    __shared__ __align__(16) float As[2][128][20];
    __shared__ __align__(16) float Bs[2][16][128];
    int b = blockIdx.y, i0 = blockIdx.x * 128;
    int tid = threadIdx.x;
    int tx = tid & 15, ty = tid >> 4;
    int ri = tid >> 1, cb = (tid & 1) * 8;
    int lk = tid >> 4, li = (tid & 15) * 8;

    const float* s2b = g_s2 + b * KK * FF;
    u64 acc[8][4];
#pragma unroll
    for (int r = 0; r < 8; ++r)
#pragma unroll
        for (int c = 0; c < 4; ++c) acc[r][c] = 0ull;

    float4 ua0, ua1, ub0, ub1;
    const float4 z4 = make_float4(0.f, 0.f, 0.f, 0.f);

    {
        int gi = i0 + ri;
        if (gi < KK) {
            const float* p = s2b + gi * FF + cb;
            ua0 = *(const float4*)p;
            ua1 = *(const float4*)(p + 4);
        } else { ua0 = z4; ua1 = z4; }
        const float* wr = w2 + lk * FF + li;
        ub0 = *(const float4*)wr;
        ub1 = *(const float4*)(wr + 4);
        *(float4*)&As[0][ri][cb]     = ua0;
        *(float4*)&As[0][ri][cb + 4] = ua1;
        *(float4*)&Bs[0][lk][li]     = ub0;
        *(float4*)&Bs[0][lk][li + 4] = ub1;
    }
    __syncthreads();

#pragma unroll 1
    for (int s = 0; s < 8; ++s) {
        int cur = s & 1;
        if (s < 7) {
            int f0 = (s + 1) * 16;
            int gi = i0 + ri;
            if (gi < KK) {
                const float* p = s2b + gi * FF + f0 + cb;
                ua0 = *(const float4*)p;
                ua1 = *(const float4*)(p + 4);
            } else { ua0 = z4; ua1 = z4; }
            const float* wr = w2 + (f0 + lk) * FF + li;
            ub0 = *(const float4*)wr;
            ub1 = *(const float4*)(wr + 4);
        }
#pragma unroll
        for (int kk = 0; kk < 16; ++kk) {
            ulonglong2 q0 = *(const ulonglong2*)&Bs[cur][kk][tx * 8];
            ulonglong2 q1 = *(const ulonglong2*)&Bs[cur][kk][tx * 8 + 4];
            u64 bp0 = q0.x, bp1 = q0.y, bp2 = q1.x, bp3 = q1.y;
#pragma unroll
            for (int r = 0; r < 8; ++r) {
                u64 ap = pack2(As[cur][ty * 8 + r][kk]);
                acc[r][0] = ffma2(ap, bp0, acc[r][0]);
                acc[r][1] = ffma2(ap, bp1, acc[r][1]);
                acc[r][2] = ffma2(ap, bp2, acc[r][2]);
                acc[r][3] = ffma2(ap, bp3, acc[r][3]);
            }
        }
        if (s < 7) {
            int nb = (s + 1) & 1;
            *(float4*)&As[nb][ri][cb]     = ua0;
            *(float4*)&As[nb][ri][cb + 4] = ua1;
            *(float4*)&Bs[nb][lk][li]     = ub0;
            *(float4*)&Bs[nb][lk][li + 4] = ub1;
        }
        __syncthreads();
    }

    const float* x1b = g_x1 + b * KK * FF;
#pragma unroll
    for (int r = 0; r < 8; ++r) {
        int gi = i0 + ty * 8 + r;
        if (gi < KK) {
            int base = gi * FF + tx * 8;
            float* dst = out + (size_t)b * KK * FF + base;
#pragma unroll
            for (int c = 0; c < 4; ++c) {
                float2 v  = *(float2*)&acc[r][c];
                float2 bb = *(const float2*)&b2[base + 2 * c];
                float2 xx = *(const float2*)&x1b[base + 2 * c];
                float2 o;
                o.x = tanhf(v.x + bb.x + xx.x);
                o.y = tanhf(v.y + bb.y + xx.y);
                *(float2*)(dst + 2 * c) = o;
            }
        }
    }
}

// ---------------- launch ----------------
extern "C" void kernel_launch(void* const* d_in, const int* in_sizes, int n_in,
                              void* d_out, int out_size) {
    const float* feat = (const float*)d_in[0];
    const float* pred = (const float*)d_in[1];
    const float* w1   = (const float*)d_in[2];
    const float* b1   = (const float*)d_in[3];
    const float* w2   = (const float*)d_in[4];
    const float* b2   = (const float*)d_in[5];
    float* out = (float*)d_out;

    const int feat_elems = BB * KK * FF;
    float* out_idx = (out_size >= feat_elems + BB * KK) ? (out + feat_elems) : (float*)0;

    prep_w1<<<128, 256>>>(w1);
    topk_kernel<<<BB, 1024>>>(pred, out_idx);
    nbr_kernel<<<(BB * KK + 255) / 256, 256>>>();
    {
        dim3 grid((KK + 127) / 128, BB);
        gemm1_mma<<<grid, 256>>>(feat);
    }
    x1_kernel<<<BB * KK / 8, 256>>>(b1);
    s2_kernel<<<BB * KK / 8, 256>>>();
    {
        dim3 grid((KK + 127) / 128, BB);
        gemm2_kernel<<<grid, 256>>>(w2, b2, out);
    }
}

// round 8
// speedup vs baseline: 1.7094x; 1.1561x over previous
#include <cuda_runtime.h>
#include <math.h>

#define BB 8
#define CC 512
#define HH 75
#define WW 100
#define PP 7500
#define KK 2000
#define FF 128

typedef unsigned long long u64;
typedef unsigned int u32;

#define CLIP(x) fminf(fmaxf((x), 0.0f), 6.0f)

__device__ __forceinline__ u32 f2tf32(float x) {
    u32 u;
    asm("cvt.rna.tf32.f32 %0, %1;" : "=r"(u) : "f"(x));
    return u;
}
__device__ __forceinline__ void mma8(float* d, u32 a0, u32 a1, u32 a2, u32 a3,
                                     u32 b0, u32 b1) {
    asm volatile(
        "mma.sync.aligned.m16n8k8.row.col.f32.tf32.tf32.f32 "
        "{%0,%1,%2,%3}, {%4,%5,%6,%7}, {%8,%9}, {%0,%1,%2,%3};"
        : "+f"(d[0]), "+f"(d[1]), "+f"(d[2]), "+f"(d[3])
        : "r"(a0), "r"(a1), "r"(a2), "r"(a3), "r"(b0), "r"(b1));
}

// ---------------- scratch ----------------
__device__ int   g_sorted[BB * KK];
__device__ int   g_rank[BB * PP];
__device__ int   g_nbr[BB * KK * 9];
__device__ int   g_pix[BB * KK];
__device__ float g_t1[BB * KK * FF];
__device__ float g_x1[BB * KK * FF];
__device__ float g_s2[BB * KK * FF];
// w1 frags: [kb(64)][ntg(16)][lane(32)] = {b0_hi, b1_hi, b0_lo, b1_lo}
__device__ uint4 g_w1f4[64 * 16 * 32];
// w2 frags: [kb(16)][ntg(16)][lane(32)]
__device__ uint4 g_w2f4[16 * 16 * 32];

// ---------------- block-wide exclusive scan (blockDim == 1024) ----------------
__device__ __forceinline__ int block_excl_scan(int v, int* warp_sums, int tid) {
    int lane = tid & 31, wid = tid >> 5;
    int x = v;
#pragma unroll
    for (int o = 1; o < 32; o <<= 1) {
        int y = __shfl_up_sync(0xFFFFFFFFu, x, o);
        if (lane >= o) x += y;
    }
    if (lane == 31) warp_sums[wid] = x;
    __syncthreads();
    if (wid == 0) {
        int s = warp_sums[lane];
        int orig = s;
#pragma unroll
        for (int o = 1; o < 32; o <<= 1) {
            int y = __shfl_up_sync(0xFFFFFFFFu, s, o);
            if (lane >= o) s += y;
        }
        warp_sums[lane] = s - orig;
    }
    __syncthreads();
    return (x - v) + warp_sums[wid];
}

// ---------------- K0a/K0b: split weights into tf32 hi/lo fragment tables ----------------
__global__ void __launch_bounds__(256) prep_w1(const float* __restrict__ w1) {
    int t = blockIdx.x * blockDim.x + threadIdx.x;
    if (t >= 64 * 16 * 32) return;
    int lane = t & 31;
    int ntg  = (t >> 5) & 15;
    int kb   = t >> 9;
    int n  = ntg * 8 + (lane >> 2);
    int k0 = kb * 8 + (lane & 3);
    float v0 = w1[k0 * FF + n];
    float v1 = w1[(k0 + 4) * FF + n];
    u32 h0 = f2tf32(v0);
    u32 h1 = f2tf32(v1);
    u32 l0 = f2tf32(v0 - __uint_as_float(h0));
    u32 l1 = f2tf32(v1 - __uint_as_float(h1));
    g_w1f4[t] = make_uint4(h0, h1, l0, l1);
}
__global__ void __launch_bounds__(256) prep_w2(const float* __restrict__ w2) {
    int t = blockIdx.x * blockDim.x + threadIdx.x;
    if (t >= 16 * 16 * 32) return;
    int lane = t & 31;
    int ntg  = (t >> 5) & 15;
    int kb   = t >> 9;
    int n  = ntg * 8 + (lane >> 2);
    int k0 = kb * 8 + (lane & 3);
    float v0 = w2[k0 * FF + n];
    float v1 = w2[(k0 + 4) * FF + n];
    u32 h0 = f2tf32(v0);
    u32 h1 = f2tf32(v1);
    u32 l0 = f2tf32(v0 - __uint_as_float(h0));
    u32 l1 = f2tf32(v1 - __uint_as_float(h1));
    g_w2f4[t] = make_uint4(h0, h1, l0, l1);
}

// ---------------- K1: per-batch top-2000 radix select + stable compaction ----------------
__global__ void __launch_bounds__(1024) topk_kernel(const float* __restrict__ pred,
                                                    float* __restrict__ out_idx) {
    int b = blockIdx.x;
    const float* sc = pred + (size_t)b * 3 * PP;
    __shared__ unsigned keys[PP];
    __shared__ unsigned hist[256];
    __shared__ int sh_bin;
    __shared__ unsigned sh_r2;
    __shared__ int warp_sums[32];
    int tid = threadIdx.x;

    for (int i = tid; i < PP; i += 1024) {
        unsigned u = __float_as_uint(sc[i]);
        u = (u & 0x80000000u) ? ~u : (u | 0x80000000u);
        keys[i] = u;
    }
    for (int i = tid; i < PP; i += 1024) g_rank[b * PP + i] = -1;
    __syncthreads();

    unsigned prefix = 0, r = KK;
#pragma unroll
    for (int pass = 0; pass < 4; ++pass) {
        int shift = 24 - 8 * pass;
        unsigned mask_hi = (pass == 0) ? 0u : (0xFFFFFFFFu << (shift + 8));
        for (int i = tid; i < 256; i += 1024) hist[i] = 0;
        __syncthreads();
        for (int i = tid; i < PP; i += 1024) {
            unsigned u = keys[i];
            if ((u & mask_hi) == prefix)
                atomicAdd(&hist[(u >> shift) & 255u], 1u);
        }
        __syncthreads();
        int v = (tid < 256) ? (int)hist[255 - tid] : 0;
        int ex = block_excl_scan(v, warp_sums, tid);
        if (tid < 256 && ex < (int)r && ex + v >= (int)r) {
            sh_bin = 255 - tid;
            sh_r2  = r - (unsigned)ex;
        }
        __syncthreads();
        prefix |= ((unsigned)sh_bin) << shift;
        r = sh_r2;
        __syncthreads();
    }
    unsigned T = prefix;

    int start = tid * 8;
    int cnt_gt = 0, cnt_eq = 0;
#pragma unroll
    for (int k = 0; k < 8; ++k) {
        int i = start + k;
        if (i < PP) {
            unsigned u = keys[i];
            cnt_gt += (u > T);
            cnt_eq += (u == T);
        }
    }
    int base_eq = block_excl_scan(cnt_eq, warp_sums, tid);
    __syncthreads();
    int need = (int)r - base_eq;
    if (need < 0) need = 0;
    if (need > cnt_eq) need = cnt_eq;
    int my_sel = cnt_gt + need;
    int base_out = block_excl_scan(my_sel, warp_sums, tid);

    int pos = base_out, eqr = base_eq;
    for (int k = 0; k < 8; ++k) {
        int i = start + k;
        if (i >= PP) break;
        unsigned u = keys[i];
        bool sel = (u > T);
        if (u == T) { if (eqr < (int)r) sel = true; eqr++; }
        if (sel) {
            g_sorted[b * KK + pos] = i;
            if (out_idx) out_idx[b * KK + pos] = (float)i;
            g_rank[b * PP + i] = pos;
            pos++;
        }
    }
}

// ---------------- K2: neighbor lists + feature pixel offsets ----------------
__global__ void nbr_kernel() {
    int t = blockIdx.x * blockDim.x + threadIdx.x;
    if (t >= BB * KK) return;
    int b = t / KK;
    int s = g_sorted[t];
    int py = s / WW, px = s % WW;
    g_pix[t] = (s % HH) * WW + (s / HH);
#pragma unroll
    for (int q = 0; q < 9; ++q) {
        int dy = q / 3 - 1, dx = q % 3 - 1;
        int ny = py + dy, nx = px + dx;
        int v = -1;
        if (ny >= 0 && ny < HH && nx >= 0 && nx < WW)
            v = g_rank[b * PP + ny * WW + nx];
        g_nbr[t * 9 + q] = v;
    }
}

// ---------------- K3: fused gather + GEMM1 on tensor cores (split tf32) ----------------
// CTA tile 64i x 128f, 32 k-stages of 16; 8 warps = 2(m) x 4(n), warp tile 32x32.
// 2 CTAs/SM for latency hiding.
#define APAD 72
__global__ void __launch_bounds__(256, 2) gemm1_mma(const float* __restrict__ feat) {
    __shared__ u32 Ah[2][16 * APAD];
    __shared__ u32 Al[2][16 * APAD];
    __shared__ int pixS[64];
    int b = blockIdx.y, i0 = blockIdx.x * 64;
    int tid = threadIdx.x;
    int lane = tid & 31, warp = tid >> 5;
    int wm = warp & 1, wn = warp >> 1;
    int lk = tid >> 4, li = (tid & 15) * 4;   // loader: channel row lk, 4 pixels

    if (tid < 64) {
        int gi = i0 + tid;
        pixS[tid] = (gi < KK) ? g_pix[b * KK + gi] : 0;
    }
    __syncthreads();

    const float* fb = feat + (size_t)b * CC * PP;
    float acc[2][4][4];
#pragma unroll
    for (int mt = 0; mt < 2; ++mt)
#pragma unroll
        for (int nt = 0; nt < 4; ++nt)
#pragma unroll
            for (int e = 0; e < 4; ++e) acc[mt][nt][e] = 0.0f;

    // prologue: stage 0
    {
        const float* fr = fb + (size_t)lk * PP;
        float ra[4];
#pragma unroll
        for (int j = 0; j < 4; ++j) ra[j] = CLIP(fr[pixS[li + j]]);
        u32 h[4], l[4];
#pragma unroll
        for (int j = 0; j < 4; ++j) {
            h[j] = f2tf32(ra[j]);
            l[j] = f2tf32(ra[j] - __uint_as_float(h[j]));
        }
        *(uint4*)&Ah[0][lk * APAD + li] = make_uint4(h[0], h[1], h[2], h[3]);
        *(uint4*)&Al[0][lk * APAD + li] = make_uint4(l[0], l[1], l[2], l[3]);
    }
    __syncthreads();

    int r4 = lane >> 2, c4 = lane & 3;

#pragma unroll 1
    for (int s = 0; s < 32; ++s) {
        int cur = s & 1;
        float ra[4];
        if (s < 31) {
            const float* fr = fb + (size_t)((s + 1) * 16 + lk) * PP;
#pragma unroll
            for (int j = 0; j < 4; ++j) ra[j] = CLIP(fr[pixS[li + j]]);
        }
        uint4 bf[2][4];
#pragma unroll
        for (int kq = 0; kq < 2; ++kq)
#pragma unroll
            for (int nt = 0; nt < 4; ++nt)
                bf[kq][nt] = g_w1f4[(((2 * s + kq) * 16) + wn * 4 + nt) * 32 + lane];

#pragma unroll
        for (int kq = 0; kq < 2; ++kq) {
#pragma unroll
            for (int mt = 0; mt < 2; ++mt) {
                int mb = wm * 32 + mt * 16 + r4;
                int k0 = (kq * 8 + c4) * APAD;
                int k4 = (kq * 8 + 4 + c4) * APAD;
                u32 ah0 = Ah[cur][k0 + mb];
                u32 ah1 = Ah[cur][k0 + mb + 8];
                u32 ah2 = Ah[cur][k4 + mb];
                u32 ah3 = Ah[cur][k4 + mb + 8];
                u32 al0 = Al[cur][k0 + mb];
                u32 al1 = Al[cur][k0 + mb + 8];
                u32 al2 = Al[cur][k4 + mb];
                u32 al3 = Al[cur][k4 + mb + 8];
#pragma unroll
                for (int nt = 0; nt < 4; ++nt) {
                    uint4 bb = bf[kq][nt];
                    mma8(acc[mt][nt], ah0, ah1, ah2, ah3, bb.x, bb.y);
                    mma8(acc[mt][nt], ah0, ah1, ah2, ah3, bb.z, bb.w);
                    mma8(acc[mt][nt], al0, al1, al2, al3, bb.x, bb.y);
                }
            }
        }
        if (s < 31) {
            int nb = (s + 1) & 1;
            u32 h[4], l[4];
#pragma unroll
            for (int j = 0; j < 4; ++j) {
                h[j] = f2tf32(ra[j]);
                l[j] = f2tf32(ra[j] - __uint_as_float(h[j]));
            }
            *(uint4*)&Ah[nb][lk * APAD + li] = make_uint4(h[0], h[1], h[2], h[3]);
            *(uint4*)&Al[nb][lk * APAD + li] = make_uint4(l[0], l[1], l[2], l[3]);
        }
        __syncthreads();
    }

    float* t1b = g_t1 + b * KK * FF;
#pragma unroll
    for (int mt = 0; mt < 2; ++mt) {
#pragma unroll
        for (int nt = 0; nt < 4; ++nt) {
            int m = wm * 32 + mt * 16 + r4;
            int n = wn * 32 + nt * 8 + 2 * c4;
            int gi = i0 + m;
            if (gi < KK)
                *(float2*)&t1b[gi * FF + n] = make_float2(acc[mt][nt][0], acc[mt][nt][1]);
            int gi8 = gi + 8;
            if (gi8 < KK)
                *(float2*)&t1b[gi8 * FF + n] = make_float2(acc[mt][nt][2], acc[mt][nt][3]);
        }
    }
}

// ---------------- K4: x1 = A @ t1 + b1 (float4, 8 rows/block) ----------------
__global__ void __launch_bounds__(256) x1_kernel(const float* __restrict__ b1) {
    int r = blockIdx.x * 8 + (threadIdx.x >> 5);
    int lane = threadIdx.x & 31;
    int b = r / KK, i = r % KK;
    const int* nb = g_nbr + r * 9;
    const float* t1b = g_t1 + b * KK * FF;
    float4 s = *(const float4*)&b1[i * FF + lane * 4];
#pragma unroll
    for (int q = 0; q < 9; ++q) {
        int j = nb[q];
        if (j >= 0) {
            float4 t = *(const float4*)&t1b[j * FF + lane * 4];
            s.x += t.x; s.y += t.y; s.z += t.z; s.w += t.w;
        }
    }
    *(float4*)&g_x1[r * FF + lane * 4] = s;
}

// ---------------- K5: s2 = A @ x1 ----------------
__global__ void __launch_bounds__(256) s2_kernel() {
    int r = blockIdx.x * 8 + (threadIdx.x >> 5);
    int lane = threadIdx.x & 31;
    int b = r / KK;
    const int* nb = g_nbr + r * 9;
    const float* x1b = g_x1 + b * KK * FF;
    float4 s = make_float4(0.f, 0.f, 0.f, 0.f);
#pragma unroll
    for (int q = 0; q < 9; ++q) {
        int j = nb[q];
        if (j >= 0) {
            float4 t = *(const float4*)&x1b[j * FF + lane * 4];
            s.x += t.x; s.y += t.y; s.z += t.z; s.w += t.w;
        }
    }
    *(float4*)&g_s2[r * FF + lane * 4] = s;
}

// ---------------- K6: out = tanh(s2 @ w2 + b2 + x1) on tensor cores ----------------
// CTA tile 64i x 128f, K=128 in 8 stages of 16; same warp layout as gemm1.
__global__ void __launch_bounds__(256, 2) gemm2_mma(const float* __restrict__ b2,
                                                    float* __restrict__ out) {
    __shared__ u32 Ah[2][16 * APAD];
    __shared__ u32 Al[2][16 * APAD];
    int b = blockIdx.y, i0 = blockIdx.x * 64;
    int tid = threadIdx.x;
    int lane = tid & 31, warp = tid >> 5;
    int wm = warp & 1, wn = warp >> 1;
    int ri = tid >> 2, kc = (tid & 3) * 4;    // loader: row ri (0..63), 4 k-cols

    const float* s2b = g_s2 + b * KK * FF;
    float acc[2][4][4];
#pragma unroll
    for (int mt = 0; mt < 2; ++mt)
#pragma unroll
        for (int nt = 0; nt < 4; ++nt)
#pragma unroll
            for (int e = 0; e < 4; ++e) acc[mt][nt][e] = 0.0f;

    // prologue: stage 0
    {
        int gi = i0 + ri;
        float4 v = (gi < KK) ? *(const float4*)&s2b[gi * FF + kc]
                             : make_float4(0.f, 0.f, 0.f, 0.f);
        float ra[4] = {v.x, v.y, v.z, v.w};
#pragma unroll
        for (int j = 0; j < 4; ++j) {
            u32 h = f2tf32(ra[j]);
            Ah[0][(kc + j) * APAD + ri] = h;
            Al[0][(kc + j) * APAD + ri] = f2tf32(ra[j] - __uint_as_float(h));
        }
    }
    __syncthreads();

    int r4 = lane >> 2, c4 = lane & 3;

#pragma unroll 1
    for (int s = 0; s < 8; ++s) {
        int cur = s & 1;
        float ra[4];
        if (s < 7) {
            int gi = i0 + ri;
            float4 v = (gi < KK) ? *(const float4*)&s2b[gi * FF + (s + 1) * 16 + kc]
                                 : make_float4(0.f, 0.f, 0.f, 0.f);
            ra[0] = v.x; ra[1] = v.y; ra[2] = v.z; ra[3] = v.w;
        }
        uint4 bf[2][4];
#pragma unroll
        for (int kq = 0; kq < 2; ++kq)
#pragma unroll
            for (int nt = 0; nt < 4; ++nt)
                bf[kq][nt] = g_w2f4[(((2 * s + kq) * 16) + wn * 4 + nt) * 32 + lane];

#pragma unroll
        for (int kq = 0; kq < 2; ++kq) {
#pragma unroll
            for (int mt = 0; mt < 2; ++mt) {
                int mb = wm * 32 + mt * 16 + r4;
                int k0 = (kq * 8 + c4) * APAD;
                int k4 = (kq * 8 + 4 + c4) * APAD;
                u32 ah0 = Ah[cur][k0 + mb];
                u32 ah1 = Ah[cur][k0 + mb + 8];
                u32 ah2 = Ah[cur][k4 + mb];
                u32 ah3 = Ah[cur][k4 + mb + 8];
                u32 al0 = Al[cur][k0 + mb];
                u32 al1 = Al[cur][k0 + mb + 8];
                u32 al2 = Al[cur][k4 + mb];
                u32 al3 = Al[cur][k4 + mb + 8];
#pragma unroll
                for (int nt = 0; nt < 4; ++nt) {
                    uint4 bb = bf[kq][nt];
                    mma8(acc[mt][nt], ah0, ah1, ah2, ah3, bb.x, bb.y);
                    mma8(acc[mt][nt], ah0, ah1, ah2, ah3, bb.z, bb.w);
                    mma8(acc[mt][nt], al0, al1, al2, al3, bb.x, bb.y);
                }
            }
        }
        if (s < 7) {
            int nb = (s + 1) & 1;
#pragma unroll
            for (int j = 0; j < 4; ++j) {
                u32 h = f2tf32(ra[j]);
                Ah[nb][(kc + j) * APAD + ri] = h;
                Al[nb][(kc + j) * APAD + ri] = f2tf32(ra[j] - __uint_as_float(h));
            }
        }
        __syncthreads();
    }

    const float* x1b = g_x1 + b * KK * FF;
#pragma unroll
    for (int mt = 0; mt < 2; ++mt) {
#pragma unroll
        for (int nt = 0; nt < 4; ++nt) {
            int m = wm * 32 + mt * 16 + r4;
            int n = wn * 32 + nt * 8 + 2 * c4;
#pragma unroll
            for (int half = 0; half < 2; ++half) {
                int gi = i0 + m + half * 8;
                if (gi < KK) {
                    int base = gi * FF + n;
                    float2 bb = *(const float2*)&b2[base];
                    float2 xx = *(const float2*)&x1b[base];
                    float2 o;
                    o.x = tanhf(acc[mt][nt][half * 2 + 0] + bb.x + xx.x);
                    o.y = tanhf(acc[mt][nt][half * 2 + 1] + bb.y + xx.y);
                    *(float2*)&out[(size_t)b * KK * FF + base] = o;
                }
            }
        }
    }
}

// ---------------- launch ----------------
extern "C" void kernel_launch(void* const* d_in, const int* in_sizes, int n_in,
                              void* d_out, int out_size) {
    const float* feat = (const float*)d_in[0];
    const float* pred = (const float*)d_in[1];
    const float* w1   = (const float*)d_in[2];
    const float* b1   = (const float*)d_in[3];
    const float* w2   = (const float*)d_in[4];
    const float* b2   = (const float*)d_in[5];
    float* out = (float*)d_out;

    const int feat_elems = BB * KK * FF;
    float* out_idx = (out_size >= feat_elems + BB * KK) ? (out + feat_elems) : (float*)0;

    prep_w1<<<128, 256>>>(w1);
    prep_w2<<<32, 256>>>(w2);
    topk_kernel<<<BB, 1024>>>(pred, out_idx);
    nbr_kernel<<<(BB * KK + 255) / 256, 256>>>();
    {
        dim3 grid((KK + 63) / 64, BB);
        gemm1_mma<<<grid, 256>>>(feat);
    }
    x1_kernel<<<BB * KK / 8, 256>>>(b1);
    s2_kernel<<<BB * KK / 8, 256>>>();
    {
        dim3 grid((KK + 63) / 64, BB);
        gemm2_mma<<<grid, 256>>>(b2, out);
    }
}

// round 9
// speedup vs baseline: 1.9481x; 1.1396x over previous
#include <cuda_runtime.h>
#include <math.h>

#define BB 8
#define CC 512
#define HH 75
#define WW 100
#define PP 7500
#define KK 2000
#define FF 128

typedef unsigned long long u64;
typedef unsigned int u32;

#define CLIP(x) fminf(fmaxf((x), 0.0f), 6.0f)

// pack two f32 into bf16x2: result.lo = lo_elem, result.hi = hi_elem
__device__ __forceinline__ u32 packbf2(float lo_elem, float hi_elem) {
    u32 r;
    asm("cvt.rn.bf16x2.f32 %0, %1, %2;" : "=r"(r) : "f"(hi_elem), "f"(lo_elem));
    return r;
}
__device__ __forceinline__ float bf_lo(u32 p) { return __uint_as_float(p << 16); }
__device__ __forceinline__ float bf_hi(u32 p) { return __uint_as_float(p & 0xFFFF0000u); }

__device__ __forceinline__ void mma16(float* d, u32 a0, u32 a1, u32 a2, u32 a3,
                                      u32 b0, u32 b1) {
    asm volatile(
        "mma.sync.aligned.m16n8k16.row.col.f32.bf16.bf16.f32 "
        "{%0,%1,%2,%3}, {%4,%5,%6,%7}, {%8,%9}, {%0,%1,%2,%3};"
        : "+f"(d[0]), "+f"(d[1]), "+f"(d[2]), "+f"(d[3])
        : "r"(a0), "r"(a1), "r"(a2), "r"(a3), "r"(b0), "r"(b1));
}

// ---------------- scratch ----------------
__device__ int   g_sorted[BB * KK];
__device__ int   g_rank[BB * PP];
__device__ int   g_nbr[BB * KK * 9];
__device__ int   g_pix[BB * KK];
__device__ float g_t1[BB * KK * FF];
__device__ float g_x1[BB * KK * FF];
__device__ float g_s2[BB * KK * FF];
// bf16 hi/lo fragment tables: entry = {b0_hi, b1_hi, b0_lo, b1_lo}
// w1: [kb(32)][ntg(16)][lane(32)] ; w2: [kb(8)][ntg(16)][lane(32)]
__device__ uint4 g_w1f4[32 * 16 * 32];
__device__ uint4 g_w2f4[8 * 16 * 32];

// ---------------- block-wide exclusive scan (blockDim == 1024) ----------------
__device__ __forceinline__ int block_excl_scan(int v, int* warp_sums, int tid) {
    int lane = tid & 31, wid = tid >> 5;
    int x = v;
#pragma unroll
    for (int o = 1; o < 32; o <<= 1) {
        int y = __shfl_up_sync(0xFFFFFFFFu, x, o);
        if (lane >= o) x += y;
    }
    if (lane == 31) warp_sums[wid] = x;
    __syncthreads();
    if (wid == 0) {
        int s = warp_sums[lane];
        int orig = s;
#pragma unroll
        for (int o = 1; o < 32; o <<= 1) {
            int y = __shfl_up_sync(0xFFFFFFFFu, s, o);
            if (lane >= o) s += y;
        }
        warp_sums[lane] = s - orig;
    }
    __syncthreads();
    return (x - v) + warp_sums[wid];
}

// ---------------- weight split helper ----------------
__device__ __forceinline__ uint4 split_frag(const float* w, int k0, int n) {
    float v0 = w[k0 * FF + n];
    float v1 = w[(k0 + 1) * FF + n];
    float v2 = w[(k0 + 8) * FF + n];
    float v3 = w[(k0 + 9) * FF + n];
    u32 b0h = packbf2(v0, v1);
    u32 b1h = packbf2(v2, v3);
    u32 b0l = packbf2(v0 - bf_lo(b0h), v1 - bf_hi(b0h));
    u32 b1l = packbf2(v2 - bf_lo(b1h), v3 - bf_hi(b1h));
    return make_uint4(b0h, b1h, b0l, b1l);
}

// ---------------- K1: setup = topk + nbr (blocks 0..7) | weight prep (blocks 8..27) ----------------
__global__ void __launch_bounds__(1024) setup_kernel(const float* __restrict__ pred,
                                                     const float* __restrict__ w1,
                                                     const float* __restrict__ w2,
                                                     float* __restrict__ out_idx) {
    int tid = threadIdx.x;
    if (blockIdx.x >= 8) {
        // ---- weight prep ----
        int t = (blockIdx.x - 8) * 1024 + tid;
        if (t < 32 * 16 * 32) {
            int lane = t & 31;
            int ntg  = (t >> 5) & 15;
            int kb   = t >> 9;
            int n  = ntg * 8 + (lane >> 2);
            int k0 = kb * 16 + 2 * (lane & 3);
            g_w1f4[t] = split_frag(w1, k0, n);
        } else if (t < 32 * 16 * 32 + 8 * 16 * 32) {
            int t2 = t - 32 * 16 * 32;
            int lane = t2 & 31;
            int ntg  = (t2 >> 5) & 15;
            int kb   = t2 >> 9;
            int n  = ntg * 8 + (lane >> 2);
            int k0 = kb * 16 + 2 * (lane & 3);
            g_w2f4[t2] = split_frag(w2, k0, n);
        }
        return;
    }
    // ---- topk ----
    int b = blockIdx.x;
    const float* sc = pred + (size_t)b * 3 * PP;
    __shared__ unsigned keys[PP];
    __shared__ unsigned hist[256];
    __shared__ int sh_bin;
    __shared__ unsigned sh_r2;
    __shared__ int warp_sums[32];

    for (int i = tid; i < PP; i += 1024) {
        unsigned u = __float_as_uint(sc[i]);
        u = (u & 0x80000000u) ? ~u : (u | 0x80000000u);
        keys[i] = u;
    }
    for (int i = tid; i < PP; i += 1024) g_rank[b * PP + i] = -1;
    __syncthreads();

    unsigned prefix = 0, r = KK;
#pragma unroll
    for (int pass = 0; pass < 4; ++pass) {
        int shift = 24 - 8 * pass;
        unsigned mask_hi = (pass == 0) ? 0u : (0xFFFFFFFFu << (shift + 8));
        for (int i = tid; i < 256; i += 1024) hist[i] = 0;
        __syncthreads();
        for (int i = tid; i < PP; i += 1024) {
            unsigned u = keys[i];
            if ((u & mask_hi) == prefix)
                atomicAdd(&hist[(u >> shift) & 255u], 1u);
        }
        __syncthreads();
        int v = (tid < 256) ? (int)hist[255 - tid] : 0;
        int ex = block_excl_scan(v, warp_sums, tid);
        if (tid < 256 && ex < (int)r && ex + v >= (int)r) {
            sh_bin = 255 - tid;
            sh_r2  = r - (unsigned)ex;
        }
        __syncthreads();
        prefix |= ((unsigned)sh_bin) << shift;
        r = sh_r2;
        __syncthreads();
    }
    unsigned T = prefix;

    int start = tid * 8;
    int cnt_gt = 0, cnt_eq = 0;
#pragma unroll
    for (int k = 0; k < 8; ++k) {
        int i = start + k;
        if (i < PP) {
            unsigned u = keys[i];
            cnt_gt += (u > T);
            cnt_eq += (u == T);
        }
    }
    int base_eq = block_excl_scan(cnt_eq, warp_sums, tid);
    __syncthreads();
    int need = (int)r - base_eq;
    if (need < 0) need = 0;
    if (need > cnt_eq) need = cnt_eq;
    int my_sel = cnt_gt + need;
    int base_out = block_excl_scan(my_sel, warp_sums, tid);

    int pos = base_out, eqr = base_eq;
    for (int k = 0; k < 8; ++k) {
        int i = start + k;
        if (i >= PP) break;
        unsigned u = keys[i];
        bool sel = (u > T);
        if (u == T) { if (eqr < (int)r) sel = true; eqr++; }
        if (sel) {
            g_sorted[b * KK + pos] = i;
            if (out_idx) out_idx[b * KK + pos] = (float)i;
            g_rank[b * PP + i] = pos;
            g_pix[b * KK + pos] = (i % HH) * WW + (i / HH);
            pos++;
        }
    }
    __syncthreads();   // g_sorted / g_rank visible block-wide

    // ---- nbr (fused) ----
    for (int i = tid; i < KK; i += 1024) {
        int s = g_sorted[b * KK + i];
        int py = s / WW, px = s % WW;
        const int* rk = g_rank + b * PP;
        int* nb = g_nbr + (b * KK + i) * 9;
#pragma unroll
        for (int q = 0; q < 9; ++q) {
            int dy = q / 3 - 1, dx = q % 3 - 1;
            int ny = py + dy, nx = px + dx;
            int v = -1;
            if (ny >= 0 && ny < HH && nx >= 0 && nx < WW)
                v = rk[ny * WW + nx];
            nb[q] = v;
        }
    }
}

// ---------------- K2: fused gather + GEMM1, bf16 3-term split MMA ----------------
// CTA tile 64i x 128f; 32 k-stages of 16; 8 warps = 2(m) x 4(n), warp tile 32x32.
// A smem: [k2(8)][m(64)] packed bf16x2, stride 72 (conflict-free).
#define AST 72
__global__ void __launch_bounds__(256, 2) gemm1_mma(const float* __restrict__ feat) {
    __shared__ u32 AhS[2][8 * AST];
    __shared__ u32 AlS[2][8 * AST];
    __shared__ int pixS[64];
    int b = blockIdx.y, i0 = blockIdx.x * 64;
    int tid = threadIdx.x;
    int lane = tid & 31, warp = tid >> 5;
    int wm = warp & 1, wn = warp >> 1;
    int lm = tid & 63, lcg = tid >> 6;        // loader: pixel lm, channel group lcg*4

    if (tid < 64) {
        int gi = i0 + tid;
        pixS[tid] = (gi < KK) ? g_pix[b * KK + gi] : 0;
    }
    __syncthreads();

    const float* fb = feat + (size_t)b * CC * PP;
    float acc[2][4][4];
#pragma unroll
    for (int mt = 0; mt < 2; ++mt)
#pragma unroll
        for (int nt = 0; nt < 4; ++nt)
#pragma unroll
            for (int e = 0; e < 4; ++e) acc[mt][nt][e] = 0.0f;

    int mypix = pixS[lm];
    // prologue stage 0
    {
        const float* fp = fb + (size_t)(lcg * 4) * PP + mypix;
        float v0 = CLIP(fp[0]);
        float v1 = CLIP(fp[PP]);
        float v2 = CLIP(fp[2 * PP]);
        float v3 = CLIP(fp[3 * PP]);
        u32 h01 = packbf2(v0, v1), h23 = packbf2(v2, v3);
        u32 l01 = packbf2(v0 - bf_lo(h01), v1 - bf_hi(h01));
        u32 l23 = packbf2(v2 - bf_lo(h23), v3 - bf_hi(h23));
        AhS[0][(lcg * 2 + 0) * AST + lm] = h01;
        AhS[0][(lcg * 2 + 1) * AST + lm] = h23;
        AlS[0][(lcg * 2 + 0) * AST + lm] = l01;
        AlS[0][(lcg * 2 + 1) * AST + lm] = l23;
    }
    __syncthreads();

    int r4 = lane >> 2, c4 = lane & 3;

#pragma unroll 1
    for (int s = 0; s < 32; ++s) {
        int cur = s & 1;
        float v0, v1, v2, v3;
        if (s < 31) {
            const float* fp = fb + (size_t)((s + 1) * 16 + lcg * 4) * PP + mypix;
            v0 = CLIP(fp[0]);
            v1 = CLIP(fp[PP]);
            v2 = CLIP(fp[2 * PP]);
            v3 = CLIP(fp[3 * PP]);
        }
        uint4 bf[4];
#pragma unroll
        for (int nt = 0; nt < 4; ++nt)
            bf[nt] = g_w1f4[(s * 16 + wn * 4 + nt) * 32 + lane];

#pragma unroll
        for (int mt = 0; mt < 2; ++mt) {
            int mb = wm * 32 + mt * 16 + r4;
            u32 ah0 = AhS[cur][c4 * AST + mb];
            u32 ah1 = AhS[cur][c4 * AST + mb + 8];
            u32 ah2 = AhS[cur][(c4 + 4) * AST + mb];
            u32 ah3 = AhS[cur][(c4 + 4) * AST + mb + 8];
            u32 al0 = AlS[cur][c4 * AST + mb];
            u32 al1 = AlS[cur][c4 * AST + mb + 8];
            u32 al2 = AlS[cur][(c4 + 4) * AST + mb];
            u32 al3 = AlS[cur][(c4 + 4) * AST + mb + 8];
#pragma unroll
            for (int nt = 0; nt < 4; ++nt) {
                uint4 bb = bf[nt];
                mma16(acc[mt][nt], ah0, ah1, ah2, ah3, bb.x, bb.y);  // hi*hi
                mma16(acc[mt][nt], ah0, ah1, ah2, ah3, bb.z, bb.w);  // hi*lo
                mma16(acc[mt][nt], al0, al1, al2, al3, bb.x, bb.y);  // lo*hi
            }
        }
        if (s < 31) {
            int nb = (s + 1) & 1;
            u32 h01 = packbf2(v0, v1), h23 = packbf2(v2, v3);
            u32 l01 = packbf2(v0 - bf_lo(h01), v1 - bf_hi(h01));
            u32 l23 = packbf2(v2 - bf_lo(h23), v3 - bf_hi(h23));
            AhS[nb][(lcg * 2 + 0) * AST + lm] = h01;
            AhS[nb][(lcg * 2 + 1) * AST + lm] = h23;
            AlS[nb][(lcg * 2 + 0) * AST + lm] = l01;
            AlS[nb][(lcg * 2 + 1) * AST + lm] = l23;
        }
        __syncthreads();
    }

    float* t1b = g_t1 + b * KK * FF;
#pragma unroll
    for (int mt = 0; mt < 2; ++mt) {
#pragma unroll
        for (int nt = 0; nt < 4; ++nt) {
            int m = wm * 32 + mt * 16 + r4;
            int n = wn * 32 + nt * 8 + 2 * c4;
            int gi = i0 + m;
            if (gi < KK)
                *(float2*)&t1b[gi * FF + n] = make_float2(acc[mt][nt][0], acc[mt][nt][1]);
            int gi8 = gi + 8;
            if (gi8 < KK)
                *(float2*)&t1b[gi8 * FF + n] = make_float2(acc[mt][nt][2], acc[mt][nt][3]);
        }
    }
}

// ---------------- K3: x1 = A @ t1 + b1 ----------------
__global__ void __launch_bounds__(256) x1_kernel(const float* __restrict__ b1) {
    int r = blockIdx.x * 8 + (threadIdx.x >> 5);
    int lane = threadIdx.x & 31;
    int b = r / KK, i = r % KK;
    const int* nb = g_nbr + r * 9;
    const float* t1b = g_t1 + b * KK * FF;
    float4 s = *(const float4*)&b1[i * FF + lane * 4];
#pragma unroll
    for (int q = 0; q < 9; ++q) {
        int j = nb[q];
        if (j >= 0) {
            float4 t = *(const float4*)&t1b[j * FF + lane * 4];
            s.x += t.x; s.y += t.y; s.z += t.z; s.w += t.w;
        }
    }
    *(float4*)&g_x1[r * FF + lane * 4] = s;
}

// ---------------- K4: s2 = A @ x1 ----------------
__global__ void __launch_bounds__(256) s2_kernel() {
    int r = blockIdx.x * 8 + (threadIdx.x >> 5);
    int lane = threadIdx.x & 31;
    int b = r / KK;
    const int* nb = g_nbr + r * 9;
    const float* x1b = g_x1 + b * KK * FF;
    float4 s = make_float4(0.f, 0.f, 0.f, 0.f);
#pragma unroll
    for (int q = 0; q < 9; ++q) {
        int j = nb[q];
        if (j >= 0) {
            float4 t = *(const float4*)&x1b[j * FF + lane * 4];
            s.x += t.x; s.y += t.y; s.z += t.z; s.w += t.w;
        }
    }
    *(float4*)&g_s2[r * FF + lane * 4] = s;
}

// ---------------- K5: out = tanh(s2 @ w2 + b2 + x1), bf16 3-term MMA ----------------
__global__ void __launch_bounds__(256, 2) gemm2_mma(const float* __restrict__ b2,
                                                    float* __restrict__ out) {
    __shared__ u32 AhS[2][8 * AST];
    __shared__ u32 AlS[2][8 * AST];
    int b = blockIdx.y, i0 = blockIdx.x * 64;
    int tid = threadIdx.x;
    int lane = tid & 31, warp = tid >> 5;
    int wm = warp & 1, wn = warp >> 1;
    int lm = tid & 63, lcg = tid >> 6;

    const float* s2b = g_s2 + b * KK * FF;
    int gi_l = i0 + lm;
    int gi_c = (gi_l < KK) ? gi_l : (KK - 1);

    float acc[2][4][4];
#pragma unroll
    for (int mt = 0; mt < 2; ++mt)
#pragma unroll
        for (int nt = 0; nt < 4; ++nt)
#pragma unroll
            for (int e = 0; e < 4; ++e) acc[mt][nt][e] = 0.0f;

    // prologue stage 0
    {
        float4 v = *(const float4*)&s2b[gi_c * FF + lcg * 4];
        u32 h01 = packbf2(v.x, v.y), h23 = packbf2(v.z, v.w);
        u32 l01 = packbf2(v.x - bf_lo(h01), v.y - bf_hi(h01));
        u32 l23 = packbf2(v.z - bf_lo(h23), v.w - bf_hi(h23));
        AhS[0][(lcg * 2 + 0) * AST + lm] = h01;
        AhS[0][(lcg * 2 + 1) * AST + lm] = h23;
        AlS[0][(lcg * 2 + 0) * AST + lm] = l01;
        AlS[0][(lcg * 2 + 1) * AST + lm] = l23;
    }
    __syncthreads();

    int r4 = lane >> 2, c4 = lane & 3;

#pragma unroll 1
    for (int s = 0; s < 8; ++s) {
        int cur = s & 1;
        float4 v;
        if (s < 7)
            v = *(const float4*)&s2b[gi_c * FF + (s + 1) * 16 + lcg * 4];
        uint4 bf[4];
#pragma unroll
        for (int nt = 0; nt < 4; ++nt)
            bf[nt] = g_w2f4[(s * 16 + wn * 4 + nt) * 32 + lane];

#pragma unroll
        for (int mt = 0; mt < 2; ++mt) {
            int mb = wm * 32 + mt * 16 + r4;
            u32 ah0 = AhS[cur][c4 * AST + mb];
            u32 ah1 = AhS[cur][c4 * AST + mb + 8];
            u32 ah2 = AhS[cur][(c4 + 4) * AST + mb];
            u32 ah3 = AhS[cur][(c4 + 4) * AST + mb + 8];
            u32 al0 = AlS[cur][c4 * AST + mb];
            u32 al1 = AlS[cur][c4 * AST + mb + 8];
            u32 al2 = AlS[cur][(c4 + 4) * AST + mb];
            u32 al3 = AlS[cur][(c4 + 4) * AST + mb + 8];
#pragma unroll
            for (int nt = 0; nt < 4; ++nt) {
                uint4 bb = bf[nt];
                mma16(acc[mt][nt], ah0, ah1, ah2, ah3, bb.x, bb.y);
                mma16(acc[mt][nt], ah0, ah1, ah2, ah3, bb.z, bb.w);
                mma16(acc[mt][nt], al0, al1, al2, al3, bb.x, bb.y);
            }
        }
        if (s < 7) {
            int nb = (s + 1) & 1;
            u32 h01 = packbf2(v.x, v.y), h23 = packbf2(v.z, v.w);
            u32 l01 = packbf2(v.x - bf_lo(h01), v.y - bf_hi(h01));
            u32 l23 = packbf2(v.z - bf_lo(h23), v.w - bf_hi(h23));
            AhS[nb][(lcg * 2 + 0) * AST + lm] = h01;
            AhS[nb][(lcg * 2 + 1) * AST + lm] = h23;
            AlS[nb][(lcg * 2 + 0) * AST + lm] = l01;
            AlS[nb][(lcg * 2 + 1) * AST + lm] = l23;
        }
        __syncthreads();
    }

    const float* x1b = g_x1 + b * KK * FF;
#pragma unroll
    for (int mt = 0; mt < 2; ++mt) {
#pragma unroll
        for (int nt = 0; nt < 4; ++nt) {
            int m = wm * 32 + mt * 16 + r4;
            int n = wn * 32 + nt * 8 + 2 * c4;
#pragma unroll
            for (int half = 0; half < 2; ++half) {
                int gi = i0 + m + half * 8;
                if (gi < KK) {
                    int base = gi * FF + n;
                    float2 bb = *(const float2*)&b2[base];
                    float2 xx = *(const float2*)&x1b[base];
                    float2 o;
                    o.x = tanhf(acc[mt][nt][half * 2 + 0] + bb.x + xx.x);
                    o.y = tanhf(acc[mt][nt][half * 2 + 1] + bb.y + xx.y);
                    *(float2*)&out[(size_t)b * KK * FF + base] = o;
                }
            }
        }
    }
}

// ---------------- launch ----------------
extern "C" void kernel_launch(void* const* d_in, const int* in_sizes, int n_in,
                              void* d_out, int out_size) {
    const float* feat = (const float*)d_in[0];
    const float* pred = (const float*)d_in[1];
    const float* w1   = (const float*)d_in[2];
    const float* b1   = (const float*)d_in[3];
    const float* w2   = (const float*)d_in[4];
    const float* b2   = (const float*)d_in[5];
    float* out = (float*)d_out;

    const int feat_elems = BB * KK * FF;
    float* out_idx = (out_size >= feat_elems + BB * KK) ? (out + feat_elems) : (float*)0;

    setup_kernel<<<28, 1024>>>(pred, w1, w2, out_idx);
    {
        dim3 grid((KK + 63) / 64, BB);
        gemm1_mma<<<grid, 256>>>(feat);
    }
    x1_kernel<<<BB * KK / 8, 256>>>(b1);
    s2_kernel<<<BB * KK / 8, 256>>>();
    {
        dim3 grid((KK + 63) / 64, BB);
        gemm2_mma<<<grid, 256>>>(b2, out);
    }
}